// round 17
// baseline (speedup 1.0000x reference)
#include <cuda_runtime.h>
#include <cuda_bf16.h>
#include <math_constants.h>

// Problem constants (fixed shapes)
#define BB 64
#define LL 512
#define HH 768
#define TT 9
#define NROWS (BB * LL)
#define NQUADS (NROWS / 4)   // 8192

#define NCH 8        // chunks per sequence
#define CHLEN 64     // steps per chunk

__device__ float g_llh[BB];
__device__ int   g_ctr = 0;
__device__ float g_logits_scratch[BB * LL * TT];   // fallback if out has no room

// ---- packed f32x2 helpers (FFMA2 via PTX) ----
__device__ __forceinline__ unsigned long long pack2(float lo, float hi) {
    unsigned long long r;
    asm("mov.b64 %0, {%1, %2};" : "=l"(r) : "f"(lo), "f"(hi));
    return r;
}
__device__ __forceinline__ void unpack2(float& lo, float& hi, unsigned long long v) {
    asm("mov.b64 {%0, %1}, %2;" : "=f"(lo), "=f"(hi) : "l"(v));
}
__device__ __forceinline__ void fma2(unsigned long long& d,
                                     unsigned long long a, unsigned long long b) {
    asm("fma.rn.f32x2 %0, %1, %2, %0;" : "+l"(d) : "l"(a), "l"(b));
}
// raw MUFU exp2 (1 instr vs libm's ~15)
__device__ __forceinline__ float ex2(float x) {
    float y;
    asm("ex2.approx.f32 %0, %1;" : "=f"(y) : "f"(x));
    return y;
}

// ---------------------------------------------------------------------------
// Kernel A: logits = hidden @ W + b
// FOUR rows per warp (8192 warps = 8192 quads), FFMA2 compute.
// W in smem as two ulonglong2 planes: WpA[k]=(w01,w23), WpB[k]=(w45,w67)
// (+ scalar t=8 plane). Per (it,kk): 2 LDS.128 + 1 LDS.32 + 4 packs +
// 16 FFMA2 + 4 FFMA. 16B lane stride -> conflict-free LDS.128.
// 1-it ping-pong prefetch; launch_bounds(256,3) -> 24 warps/SM.
// ---------------------------------------------------------------------------
__global__ __launch_bounds__(256, 3) void logits_kernel(
    const float* __restrict__ hidden,
    const float* __restrict__ W,
    const float* __restrict__ bias,
    float* __restrict__ logits)
{
    __shared__ ulonglong2 WpA[4 * 192];   // 12288 B  (w01, w23)
    __shared__ ulonglong2 WpB[4 * 192];   // 12288 B  (w45, w67)
    __shared__ float      Ws8[4 * 192];   //  3072 B
    __shared__ float      bs[TT];

    for (int k = threadIdx.x; k < HH; k += 256) {
        const float* wr = W + 9 * k;
        const int idx = (k & 3) * 192 + (k >> 2);
        WpA[idx] = make_ulonglong2(pack2(wr[0], wr[1]), pack2(wr[2], wr[3]));
        WpB[idx] = make_ulonglong2(pack2(wr[4], wr[5]), pack2(wr[6], wr[7]));
        Ws8[idx] = wr[8];
    }
    if (threadIdx.x < TT) bs[threadIdx.x] = bias[threadIdx.x];
    __syncthreads();

    const int lane = threadIdx.x & 31;
    const int qd   = blockIdx.x * 8 + (threadIdx.x >> 5);   // quad 0..8191

    const float4* hp = (const float4*)(hidden + (size_t)(4 * qd) * HH);
    // row r base (in float4): r * 192

    // accumulators: 4 rows x (4 packed pairs + 1 scalar)
    unsigned long long A[4][4];
    float a8[4];
    #pragma unroll
    for (int r = 0; r < 4; r++) {
        a8[r] = 0.f;
        #pragma unroll
        for (int p = 0; p < 4; p++) A[r][p] = 0ull;
    }

    float4 buf0[4], buf1[4];   // ping-pong: 4 rows x 1 it each

    #pragma unroll
    for (int r = 0; r < 4; r++) buf0[r] = hp[r * 192 + 0 * 32 + lane];
    #pragma unroll
    for (int r = 0; r < 4; r++) buf1[r] = hp[r * 192 + 1 * 32 + lane];

    #define COMPUTE_IT(buf, it)                                              \
    {                                                                        \
        float hx[4][4];                                                      \
        _Pragma("unroll")                                                    \
        for (int r = 0; r < 4; r++) {                                        \
            hx[r][0] = buf[r].x; hx[r][1] = buf[r].y;                        \
            hx[r][2] = buf[r].z; hx[r][3] = buf[r].w;                        \
        }                                                                    \
        _Pragma("unroll")                                                    \
        for (int kk = 0; kk < 4; kk++) {                                     \
            const int idx = kk * 192 + (it) * 32 + lane;                     \
            const ulonglong2 wab = WpA[idx];                                 \
            const ulonglong2 wcd = WpB[idx];                                 \
            const float w8 = Ws8[idx];                                       \
            _Pragma("unroll")                                                \
            for (int r = 0; r < 4; r++) {                                    \
                const unsigned long long hh = pack2(hx[r][kk], hx[r][kk]);   \
                fma2(A[r][0], hh, wab.x);                                    \
                fma2(A[r][1], hh, wab.y);                                    \
                fma2(A[r][2], hh, wcd.x);                                    \
                fma2(A[r][3], hh, wcd.y);                                    \
                a8[r] = fmaf(hx[r][kk], w8, a8[r]);                          \
            }                                                                \
        }                                                                    \
    }

    #define REFILL(buf, it)                                                  \
    {                                                                        \
        _Pragma("unroll")                                                    \
        for (int r = 0; r < 4; r++) buf[r] = hp[r * 192 + (it) * 32 + lane]; \
    }

    COMPUTE_IT(buf0, 0)  REFILL(buf0, 2)
    COMPUTE_IT(buf1, 1)  REFILL(buf1, 3)
    COMPUTE_IT(buf0, 2)  REFILL(buf0, 4)
    COMPUTE_IT(buf1, 3)  REFILL(buf1, 5)
    COMPUTE_IT(buf0, 4)
    COMPUTE_IT(buf1, 5)

    #undef COMPUTE_IT
    #undef REFILL

    // unpack accumulators
    float acc[4][TT];
    #pragma unroll
    for (int r = 0; r < 4; r++) {
        #pragma unroll
        for (int p = 0; p < 4; p++)
            unpack2(acc[r][2 * p], acc[r][2 * p + 1], A[r][p]);
        acc[r][8] = a8[r];
    }

    // fold reduce: pair (0,1) -> rw01, pair (2,3) -> rw23
    float rw01[TT], rw23[TT];
    #pragma unroll
    for (int t = 0; t < TT; t++) {
        float u = acc[0][t] + __shfl_xor_sync(0xffffffffu, acc[0][t], 16);
        float v = acc[1][t] + __shfl_xor_sync(0xffffffffu, acc[1][t], 16);
        float w = (lane < 16) ? u : v;
        w += __shfl_xor_sync(0xffffffffu, w, 8);
        w += __shfl_xor_sync(0xffffffffu, w, 4);
        w += __shfl_xor_sync(0xffffffffu, w, 2);
        w += __shfl_xor_sync(0xffffffffu, w, 1);
        rw01[t] = w;

        float u2 = acc[2][t] + __shfl_xor_sync(0xffffffffu, acc[2][t], 16);
        float v2 = acc[3][t] + __shfl_xor_sync(0xffffffffu, acc[3][t], 16);
        float w2 = (lane < 16) ? u2 : v2;
        w2 += __shfl_xor_sync(0xffffffffu, w2, 8);
        w2 += __shfl_xor_sync(0xffffffffu, w2, 4);
        w2 += __shfl_xor_sync(0xffffffffu, w2, 2);
        w2 += __shfl_xor_sync(0xffffffffu, w2, 1);
        rw23[t] = w2;
    }

    float* o = logits + (size_t)(4 * qd) * TT;
    #pragma unroll
    for (int t = 0; t < TT; t++) {
        if (lane == t) {
            o[t]          = rw01[t] + bs[t];   // row 0
            o[2 * TT + t] = rw23[t] + bs[t];   // row 2
        }
        if (lane == 16 + t) {
            o[TT + t]     = rw01[t] + bs[t];   // row 1
            o[3 * TT + t] = rw23[t] + bs[t];   // row 3
        }
    }
}

// ---------------------------------------------------------------------------
// Kernel B: per-batch CRF with chunked parallel scan + FUSED final loss
// (last block, detected via atomic ticket, reduces g_llh in fixed index
// order -> deterministic; counter self-resets for graph replay).
// All exps are raw ex2.approx MUFU ops.
// ---------------------------------------------------------------------------
__global__ __launch_bounds__(800) void crf_kernel(
    const float* __restrict__ logits,
    const int*   __restrict__ mask,
    const int*   __restrict__ labels,
    const float* __restrict__ start_trans,
    const float* __restrict__ end_trans,
    const float* __restrict__ trans,
    float* __restrict__ loss_out)
{
    __shared__ float e_s[LL * TT];
    __shared__ float ee_s[LL * TT];
    __shared__ float m_s[LL];
    __shared__ int   lab_s[LL];
    __shared__ float tr_s[TT * TT];
    __shared__ float st_s[TT];
    __shared__ float en_s[TT];
    __shared__ float M_s[NCH * TT * TT];
    __shared__ float E_s[NCH * TT];
    __shared__ float num_sh;
    __shared__ int   is_last;

    const int b    = blockIdx.x;
    const int tid  = threadIdx.x;
    const int lane = tid & 31;
    const int warp = tid >> 5;

    const float L2E = 1.4426950408889634f;
    const float LN2 = 0.6931471805599453f;

    const float* lg = logits + (size_t)b * LL * TT;
    #pragma unroll 2
    for (int i = tid; i < LL * TT; i += 800) {
        float e = lg[i];
        e_s[i]  = e;
        ee_s[i] = ex2(e * L2E);
    }
    for (int i = tid; i < LL; i += 800) {
        int l = labels[(size_t)b * LL + i];
        lab_s[i] = (l == -100) ? 0 : l;
        m_s[i]   = (float)mask[(size_t)b * LL + i];
    }
    if (tid < TT * TT) tr_s[tid] = trans[tid];
    if (tid < TT) { st_s[tid] = start_trans[tid]; en_s[tid] = end_trans[tid]; }
    __syncthreads();

    if (warp < 24) {
        const int c  = warp / 3;
        const int rg = warp % 3;
        int r = lane / 9; if (r > 2) r = 2;
        const int j = lane % 9;
        const int i = rg * 3 + r;
        const int base = r * 9;

        float et[TT];
        #pragma unroll
        for (int k = 0; k < TT; k++) et[k] = ex2(tr_s[k * TT + j] * L2E);

        float q = (j == i) ? 1.f : 0.f;
        int   E = 0;

        const int t0 = c * CHLEN + 1;
        int t1 = t0 + CHLEN; if (t1 > LL) t1 = LL;

        float eej_next = ee_s[t0 * TT + j];
        float ms_next  = m_s[t0];

        for (int t = t0; t < t1; t++) {
            const float eej = eej_next;
            const float ms  = ms_next;
            if (t + 1 < t1) {
                eej_next = ee_s[(t + 1) * TT + j];
                ms_next  = m_s[t + 1];
            }

            float p0 = __shfl_sync(0xffffffffu, q, base + 0);
            float p1 = __shfl_sync(0xffffffffu, q, base + 1);
            float p2 = __shfl_sync(0xffffffffu, q, base + 2);
            float p3 = __shfl_sync(0xffffffffu, q, base + 3);
            float p4 = __shfl_sync(0xffffffffu, q, base + 4);
            float p5 = __shfl_sync(0xffffffffu, q, base + 5);
            float p6 = __shfl_sync(0xffffffffu, q, base + 6);
            float p7 = __shfl_sync(0xffffffffu, q, base + 7);
            float p8 = __shfl_sync(0xffffffffu, q, base + 8);

            float a  = fmaf(p1, et[1], p0 * et[0]);  a  = fmaf(p2, et[2], a);
            float b2 = fmaf(p4, et[4], p3 * et[3]);  b2 = fmaf(p5, et[5], b2);
            float cc = fmaf(p7, et[7], p6 * et[6]);  cc = fmaf(p8, et[8], cc);
            float s  = ((a + b2) + cc) * eej;

            q = (ms != 0.f) ? s : q;

            if ((t & 7) == 7) {
                float pm = fmaxf(fmaxf(fmaxf(p0, p1), fmaxf(p2, p3)),
                                 fmaxf(fmaxf(p4, p5), fmaxf(p6, p7)));
                pm = fmaxf(pm, p8);
                int ex = (__float_as_int(pm) >> 23) & 0xFF;
                float sc = __int_as_float((254 - ex) << 23);
                q *= sc;
                E += ex - 127;
            }
        }

        if (lane < 27) {
            M_s[(c * TT + i) * TT + j] = q;
            if (j == 0) E_s[c * TT + i] = (float)E;
        }
    } else {
        float acc = 0.f;
        int   msum = 0;
        for (int t = lane; t < LL; t += 32) {
            msum += (m_s[t] != 0.f) ? 1 : 0;
            if (t >= 1) {
                int lp = lab_s[t - 1], lt = lab_s[t];
                acc = fmaf(tr_s[lp * TT + lt] + e_s[t * TT + lt], m_s[t], acc);
            }
        }
        #pragma unroll
        for (int off = 16; off > 0; off >>= 1) {
            acc  += __shfl_xor_sync(0xffffffffu, acc, off);
            msum += __shfl_xor_sync(0xffffffffu, msum, off);
        }
        if (lane == 0) {
            int seq_end = msum - 1;
            if (seq_end < 0) seq_end = 0;
            int l0 = lab_s[0];
            int llast = lab_s[seq_end];
            num_sh = st_s[l0] + e_s[l0] + acc + en_s[llast];
        }
    }

    __syncthreads();

    if (warp == 0) {
        const int j = (lane < TT) ? lane : (TT - 1);

        float q  = ex2((st_s[j] + e_s[j]) * L2E);
        int   Eq = 0;

        for (int c = 0; c < NCH; c++) {
            float Ek[TT];
            #pragma unroll
            for (int k = 0; k < TT; k++) Ek[k] = E_s[c * TT + k];
            float Em = Ek[0];
            #pragma unroll
            for (int k = 1; k < TT; k++) Em = fmaxf(Em, Ek[k]);

            float s = 0.f;
            #pragma unroll
            for (int k = 0; k < TT; k++) {
                float pk = __shfl_sync(0xffffffffu, q, k);
                float d  = Ek[k] - Em;
                float sc = (d > -120.f)
                         ? __int_as_float((((int)d) + 127) << 23) : 0.f;
                s = fmaf(pk * sc, M_s[(c * TT + k) * TT + j], s);
            }
            q  = s;
            Eq += (int)Em;

            float q0 = __shfl_sync(0xffffffffu, q, 0);
            float q1 = __shfl_sync(0xffffffffu, q, 1);
            float q2 = __shfl_sync(0xffffffffu, q, 2);
            float q3 = __shfl_sync(0xffffffffu, q, 3);
            float q4 = __shfl_sync(0xffffffffu, q, 4);
            float q5 = __shfl_sync(0xffffffffu, q, 5);
            float q6 = __shfl_sync(0xffffffffu, q, 6);
            float q7 = __shfl_sync(0xffffffffu, q, 7);
            float q8 = __shfl_sync(0xffffffffu, q, 8);
            float qm = fmaxf(fmaxf(fmaxf(q0, q1), fmaxf(q2, q3)),
                             fmaxf(fmaxf(q4, q5), fmaxf(q6, q7)));
            qm = fmaxf(qm, q8);
            int ex = (__float_as_int(qm) >> 23) & 0xFF;
            float sc2 = __int_as_float((254 - ex) << 23);
            q  *= sc2;
            Eq += ex - 127;
        }

        float v = (lane < TT) ? q * ex2(en_s[j] * L2E) : 0.f;
        #pragma unroll
        for (int off = 16; off > 0; off >>= 1)
            v += __shfl_xor_sync(0xffffffffu, v, off);
        float denom = LN2 * (__log2f(v) + (float)Eq);

        if (lane == 0) {
            g_llh[b] = num_sh - denom;
            __threadfence();
            int c = atomicAdd(&g_ctr, 1);
            is_last = (c == BB - 1) ? 1 : 0;
        }
    }

    __syncthreads();

    // last block: deterministic fixed-order loss reduction
    if (is_last && warp == 0) {
        __threadfence();
        float v = g_llh[lane] + g_llh[lane + 32];
        #pragma unroll
        for (int off = 16; off > 0; off >>= 1)
            v += __shfl_xor_sync(0xffffffffu, v, off);
        if (lane == 0) {
            loss_out[0] = -v * (1.0f / (float)BB);
            g_ctr = 0;   // reset for next graph replay
        }
    }
}

// ---------------------------------------------------------------------------
extern "C" void kernel_launch(void* const* d_in, const int* in_sizes, int n_in,
                              void* d_out, int out_size)
{
    const float* hidden      = (const float*)d_in[0];
    const int*   attn_mask   = (const int*)d_in[1];
    const int*   labels      = (const int*)d_in[2];   // int32 (JAX x64 disabled)
    const float* W           = (const float*)d_in[3];
    const float* bias        = (const float*)d_in[4];
    const float* start_trans = (const float*)d_in[5];
    const float* end_trans   = (const float*)d_in[6];
    const float* trans       = (const float*)d_in[7];

    float* out = (float*)d_out;

    static float* scratch = nullptr;
    if (!scratch) {
        void* p = nullptr;
        cudaGetSymbolAddress(&p, g_logits_scratch);
        scratch = (float*)p;
    }

    const int NLOG = BB * LL * TT;   // 294912
    float* loss_ptr;
    float* logits_ptr;
    if (out_size >= NLOG + 1) {          // (loss, logits) concatenated
        loss_ptr   = out;
        logits_ptr = out + 1;
    } else if (out_size == NLOG) {       // logits only
        loss_ptr   = scratch;
        logits_ptr = out;
    } else {                             // loss only
        loss_ptr   = out;
        logits_ptr = scratch;
    }

    logits_kernel<<<1024, 256>>>(hidden, W, bias, logits_ptr);
    crf_kernel<<<BB, 800>>>(logits_ptr, attn_mask, labels,
                            start_trans, end_trans, trans, loss_ptr);
}